// round 9
// baseline (speedup 1.0000x reference)
#include <cuda_runtime.h>
#include <cuda_bf16.h>
#include <math.h>

#define NG 2048
#define IMW 128
#define IMH 128
#define HW (IMW*IMH)
#define GRID 128
#define NTHREADS 256

#define TANFOVX 0.5f
#define TANFOVY 0.5f
#define FOCAL_X (IMW / (2.0f * TANFOVX))   // 128
#define FOCAL_Y (IMH / (2.0f * TANFOVY))   // 128
#define FARZ 1e10f

#define SH_C0 0.28209479177387814f
#define SH_C1 0.4886025119029199f
#define SH_C2_0 1.0925484305920792f
#define SH_C2_1 (-1.0925484305920792f)
#define SH_C2_2 0.31539156525252005f
#define SH_C2_3 (-1.0925484305920792f)
#define SH_C2_4 0.5462742152960396f
#define SH_C3_0 (-0.5900435899266435f)
#define SH_C3_1 2.890611442640554f
#define SH_C3_2 (-0.4570457994644657f)
#define SH_C3_3 0.3731763325901154f
#define SH_C3_4 (-0.4570457994644657f)
#define SH_C3_5 1.445305721320277f
#define SH_C3_6 (-0.5900435899266435f)

// Unsorted packed records
__device__ float4 g_upack0[NG];  // px, py, ca, cb
__device__ float4 g_upack1[NG];  // cc, op, cr, cg
__device__ float4 g_upack2[NG];  // cb(blue), invd, rad, id
__device__ float  g_depth[NG];
// Depth-sorted packed records
__device__ float4 g_pack0[NG];
__device__ float4 g_pack1[NG];
__device__ float4 g_pack2[NG];

// Monotone ticket grid barrier (replay-safe: target derived from ticket).
__device__ unsigned int g_bar_ctr = 0;

__device__ __forceinline__ void grid_barrier()
{
    __syncthreads();
    if (threadIdx.x == 0) {
        __threadfence();
        unsigned int ticket = atomicAdd(&g_bar_ctr, 1u);
        unsigned int target = (ticket / GRID + 1u) * GRID;
        unsigned int v;
        do {
            asm volatile("ld.acquire.gpu.u32 %0, [%1];" : "=r"(v) : "l"(&g_bar_ctr));
        } while (v < target);
    }
    __syncthreads();
}

#define CHUNK 256
#define NCHUNK (NG / CHUNK)   // 8

// Phase-3 shared state: raw double-buffered staging + per-strip index lists.
struct RasterSmem {
    float4 A[2][CHUNK];           // 8KB x2 halves -> 24KB total for A/B/C
    float4 B[2][CHUNK];
    float4 C[2][CHUNK];
    unsigned short idx[2][4][CHUNK];  // per consumer-warp strip lists (4KB)
    int cnt[2][4];
};

__global__ void __launch_bounds__(NTHREADS) fused_kernel(
    const float* __restrict__ means3D,
    const float* __restrict__ opacities,
    const float* __restrict__ dc,
    const float* __restrict__ shs,
    const float* __restrict__ scales,
    const float* __restrict__ rotations,
    const float* __restrict__ Vm,
    const float* __restrict__ Pm,
    float* __restrict__ out)
{
    __shared__ float sd[NG];          // phase 2 (8KB)
    __shared__ RasterSmem rs;         // phase 3 (~28.6KB)

    int tid  = threadIdx.x;
    int warp = tid >> 5;
    int lane = tid & 31;

    // ========================================================
    // Phase 1: preprocess. threads 0..15 own one gaussian each
    // ========================================================
    if (tid < 16) {
        int n = blockIdx.x * 16 + tid;

        float m0 = means3D[3*n+0], m1 = means3D[3*n+1], m2 = means3D[3*n+2];

        float pv0 = m0*Vm[0] + m1*Vm[4] + m2*Vm[8]  + Vm[12];
        float pv1 = m0*Vm[1] + m1*Vm[5] + m2*Vm[9]  + Vm[13];
        float pv2 = m0*Vm[2] + m1*Vm[6] + m2*Vm[10] + Vm[14];

        float ph0 = m0*Pm[0] + m1*Pm[4] + m2*Pm[8]  + Pm[12];
        float ph1 = m0*Pm[1] + m1*Pm[5] + m2*Pm[9]  + Pm[13];
        float ph3 = m0*Pm[3] + m1*Pm[7] + m2*Pm[11] + Pm[15];
        float invw = 1.0f / (ph3 + 1e-7f);
        float px = ((ph0*invw + 1.0f) * IMW - 1.0f) * 0.5f;
        float py = ((ph1*invw + 1.0f) * IMH - 1.0f) * 0.5f;

        float tz = pv2;
        float limx = 1.3f * TANFOVX, limy = 1.3f * TANFOVY;
        float tx = fminf(fmaxf(pv0 / tz, -limx), limx) * tz;
        float ty = fminf(fmaxf(pv1 / tz, -limy), limy) * tz;

        float qr = rotations[4*n+0], qx = rotations[4*n+1],
              qy = rotations[4*n+2], qz = rotations[4*n+3];
        float R00 = 1.f - 2.f*(qy*qy + qz*qz);
        float R01 = 2.f*(qx*qy - qr*qz);
        float R02 = 2.f*(qx*qz + qr*qy);
        float R10 = 2.f*(qx*qy + qr*qz);
        float R11 = 1.f - 2.f*(qx*qx + qz*qz);
        float R12 = 2.f*(qy*qz - qr*qx);
        float R20 = 2.f*(qx*qz - qr*qy);
        float R21 = 2.f*(qy*qz + qr*qx);
        float R22 = 1.f - 2.f*(qx*qx + qy*qy);

        float s0 = scales[3*n+0], s1 = scales[3*n+1], s2 = scales[3*n+2];
        float M00=R00*s0, M01=R01*s1, M02=R02*s2;
        float M10=R10*s0, M11=R11*s1, M12=R12*s2;
        float M20=R20*s0, M21=R21*s1, M22=R22*s2;
        float S00 = M00*M00 + M01*M01 + M02*M02;
        float S01 = M00*M10 + M01*M11 + M02*M12;
        float S02 = M00*M20 + M01*M21 + M02*M22;
        float S11 = M10*M10 + M11*M11 + M12*M12;
        float S12 = M10*M20 + M11*M21 + M12*M22;
        float S22 = M20*M20 + M21*M21 + M22*M22;

        float itz = 1.0f / tz;
        float J00 = FOCAL_X * itz;
        float J02 = -FOCAL_X * tx * itz * itz;
        float J11 = FOCAL_Y * itz;
        float J12 = -FOCAL_Y * ty * itz * itz;

        float T00 = J00*Vm[0] + J02*Vm[2];
        float T01 = J00*Vm[4] + J02*Vm[6];
        float T02 = J00*Vm[8] + J02*Vm[10];
        float T10 = J11*Vm[1] + J12*Vm[2];
        float T11 = J11*Vm[5] + J12*Vm[6];
        float T12 = J11*Vm[9] + J12*Vm[10];

        float A00 = T00*S00 + T01*S01 + T02*S02;
        float A01 = T00*S01 + T01*S11 + T02*S12;
        float A02 = T00*S02 + T01*S12 + T02*S22;
        float B00 = T10*S00 + T11*S01 + T12*S02;
        float B01 = T10*S01 + T11*S11 + T12*S12;
        float B02 = T10*S02 + T11*S12 + T12*S22;

        float cov00 = A00*T00 + A01*T01 + A02*T02;
        float cov01 = A00*T10 + A01*T11 + A02*T12;
        float cov11 = B00*T10 + B01*T11 + B02*T12;

        float a = cov00 + 0.3f;
        float b = cov01;
        float c = cov11 + 0.3f;
        float det = a*c - b*b;
        bool valid = (tz > 0.2f) && (det > 0.0f);
        float det_inv = (det > 0.0f) ? (1.0f / det) : 0.0f;

        float mid = 0.5f * (a + c);
        float lam1 = mid + sqrtf(fmaxf(0.1f, mid*mid - det));
        float radius = ceilf(3.0f * sqrtf(lam1));

        float invn = rsqrtf(m0*m0 + m1*m1 + m2*m2);
        float dX = m0*invn, dY = m1*invn, dZ = m2*invn;
        float xx = dX*dX, yy = dY*dY, zz = dZ*dZ;
        float xy = dX*dY, yz = dY*dZ, xz = dX*dZ;

        float col[3];
        #pragma unroll
        for (int ch = 0; ch < 3; ch++) {
            const float* sh = shs + (size_t)n*45 + ch;
            float res = SH_C0 * dc[3*n + ch];
            res += -SH_C1 * dY * sh[0*3] + SH_C1 * dZ * sh[1*3] - SH_C1 * dX * sh[2*3];
            res += SH_C2_0 * xy * sh[3*3] + SH_C2_1 * yz * sh[4*3]
                 + SH_C2_2 * (2.f*zz - xx - yy) * sh[5*3]
                 + SH_C2_3 * xz * sh[6*3] + SH_C2_4 * (xx - yy) * sh[7*3];
            res += SH_C3_0 * dY * (3.f*xx - yy) * sh[8*3]
                 + SH_C3_1 * xy * dZ * sh[9*3]
                 + SH_C3_2 * dY * (4.f*zz - xx - yy) * sh[10*3]
                 + SH_C3_3 * dZ * (2.f*zz - 3.f*xx - 3.f*yy) * sh[11*3]
                 + SH_C3_4 * dX * (4.f*zz - xx - yy) * sh[12*3]
                 + SH_C3_5 * dZ * (xx - yy) * sh[13*3]
                 + SH_C3_6 * dX * (xx - 3.f*yy) * sh[14*3];
            col[ch] = fmaxf(res + 0.5f, 0.0f);
        }

        float depth = valid ? tz : FARZ;
        float rad   = valid ? radius : 0.0f;

        g_upack0[n] = make_float4(px, py, c * det_inv, -b * det_inv);
        g_upack1[n] = make_float4(a * det_inv, opacities[n], col[0], col[1]);
        g_upack2[n] = make_float4(col[2], 1.0f / depth, rad, (float)n);
        g_depth[n]  = depth;

        out[5*HW + n] = rad;   // radii
    }

    grid_barrier();

    // ========================================================
    // Phase 2: stable rank-count argsort + scatter.
    // 16 gaussians/block over 8 warps -> 2 rounds each.
    // ========================================================
    #pragma unroll
    for (int i = tid; i < NG; i += NTHREADS) sd[i] = g_depth[i];
    __syncthreads();

    #pragma unroll
    for (int r = 0; r < 2; r++) {
        int gi = blockIdx.x * 16 + warp * 2 + r;
        float di = sd[gi];
        int cnt = 0;
        #pragma unroll 8
        for (int j = lane; j < NG; j += 32) {
            float dj = sd[j];
            cnt += (dj < di) || (dj == di && j < gi);
        }
        #pragma unroll
        for (int o = 16; o > 0; o >>= 1) cnt += __shfl_down_sync(0xffffffffu, cnt, o);
        if (lane == 0) {
            g_pack0[cnt] = g_upack0[gi];
            g_pack1[cnt] = g_upack1[gi];
            g_pack2[cnt] = g_upack2[gi];
        }
    }

    grid_barrier();

    // ========================================================
    // Phase 3: warp-specialized raster with per-strip lists.
    // Warps 0-3: consumers (pixel strip 16x2 each, blend).
    // Warps 4-7: producers (stage chunk raw + build strip lists).
    // ========================================================
    bool producer = (tid >= 128);
    int bx = blockIdx.x & 7;
    int by = blockIdx.x >> 3;

    float tx0 = (float)(bx * 16);
    float tx1 = tx0 + 15.0f;

    // consumer pixel (warp w owns rows 2w, 2w+1 of the tile)
    int lx = tid & 15;
    int ly = (tid >> 4) & 7;
    int x = bx * 16 + lx;
    int y = by * 8 + ly;
    float fx = (float)x, fy = (float)y;

    float T = producer ? 0.0f : 1.0f;   // producers always vote "done"
    float cr = 0.f, cg = 0.f, cb = 0.f, invd = 0.f;
    float maxw = 0.f;
    float best = -1.0f;

    // producer indices
    int ptid = tid - 128;        // 0..127
    int pw   = warp - 4;         // 0..3: builds list for consumer warp pw
    // strip bounds for producer warp pw (rows 2pw, 2pw+1)
    float ry0 = (float)(by * 8 + 2 * pw);
    float ry1 = ry0 + 1.0f;

    // --- producer fill: stage chunk c raw, then build strip list pw ---
    auto fill = [&](int c, int b) {
        int e0 = c * CHUNK + ptid;
        int e1 = e0 + 128;
        rs.A[b][ptid]       = g_pack0[e0];
        rs.B[b][ptid]       = g_pack1[e0];
        rs.C[b][ptid]       = g_pack2[e0];
        rs.A[b][ptid + 128] = g_pack0[e1];
        rs.B[b][ptid + 128] = g_pack1[e1];
        rs.C[b][ptid + 128] = g_pack2[e1];
        asm volatile("bar.sync 8, 128;" ::: "memory");   // staging visible to producers

        // scan all 256 entries in order against this warp's strip
        int cnt = 0;
        #pragma unroll
        for (int r = 0; r < CHUNK / 32; r++) {
            int e = r * 32 + lane;
            float px  = rs.A[b][e].x;
            float py  = rs.A[b][e].y;
            float rad = rs.C[b][e].z;
            bool keep = (rad > 0.0f) &&
                        (px >= tx0 - rad) && (px <= tx1 + rad) &&
                        (py >= ry0 - rad) && (py <= ry1 + rad);
            unsigned int m = __ballot_sync(0xffffffffu, keep);
            if (keep) {
                int pos = cnt + __popc(m & ((1u << lane) - 1u));
                rs.idx[b][pw][pos] = (unsigned short)e;
            }
            cnt += __popc(m);
        }
        if (lane == 0) rs.cnt[b][pw] = cnt;
    };

    // prologue: fill buffer 0 with chunk 0
    if (producer) fill(0, 0);
    __syncthreads();

    for (int c = 0; c < NCHUNK; c++) {
        int buf = c & 1;

        if (producer) {
            if (c + 1 < NCHUNK) fill(c + 1, buf ^ 1);
        } else {
            int cw = warp;                     // consumer warp id 0..3
            int n = rs.cnt[buf][cw];
            const unsigned short* list = rs.idx[buf][cw];
            if (T >= 1e-4f) {
                #pragma unroll 2
                for (int g = 0; g < n; g++) {
                    int e = list[g];           // broadcast LDS.U16
                    float4 A = rs.A[buf][e];   // broadcast LDS.128
                    float4 B = rs.B[buf][e];
                    float4 C = rs.C[buf][e];
                    float dx = fx - A.x;
                    float dy = fy - A.y;
                    float r  = C.z;
                    float power = -0.5f*A.z*dx*dx - 0.5f*B.x*dy*dy - A.w*dx*dy;
                    float alpha = fminf(0.99f, B.y * __expf(power));
                    bool ok = (fabsf(dx) <= r) & (fabsf(dy) <= r) &
                              (power <= 0.0f) & (alpha >= (1.0f/255.0f));
                    float a = ok ? alpha : 0.0f;
                    float w = a * T;
                    cr   += w * B.z;
                    cg   += w * B.w;
                    cb   += w * C.x;
                    invd += w * C.y;
                    bool better = (w > maxw);
                    maxw = better ? w : maxw;
                    best = better ? C.w : best;
                    T = T * (1.0f - a);
                }
            }
        }
        // handoff + early exit (producers vote done)
        if (__syncthreads_and(T < 1e-4f)) break;
    }

    if (!producer) {
        int pix = y * IMW + x;
        out[0*HW + pix] = cr;
        out[1*HW + pix] = cg;
        out[2*HW + pix] = cb;
        out[3*HW + pix] = invd;
        out[4*HW + pix] = (maxw > 0.0f) ? best : -1.0f;
    }
}

extern "C" void kernel_launch(void* const* d_in, const int* in_sizes, int n_in,
                              void* d_out, int out_size)
{
    (void)in_sizes; (void)n_in; (void)out_size;
    const float* means3D   = (const float*)d_in[0];
    const float* opacities = (const float*)d_in[2];
    const float* dc        = (const float*)d_in[3];
    const float* shs       = (const float*)d_in[4];
    const float* scales    = (const float*)d_in[5];
    const float* rotations = (const float*)d_in[6];
    const float* viewm     = (const float*)d_in[7];
    const float* projm     = (const float*)d_in[8];
    float* out = (float*)d_out;

    fused_kernel<<<GRID, NTHREADS>>>(means3D, opacities, dc, shs, scales,
                                     rotations, viewm, projm, out);
}

// round 10
// speedup vs baseline: 1.2644x; 1.2644x over previous
#include <cuda_runtime.h>
#include <cuda_bf16.h>
#include <math.h>

#define NG 2048
#define IMW 128
#define IMH 128
#define HW (IMW*IMH)
#define GRID 128
#define NTHREADS 256

#define TANFOVX 0.5f
#define TANFOVY 0.5f
#define FOCAL_X (IMW / (2.0f * TANFOVX))   // 128
#define FOCAL_Y (IMH / (2.0f * TANFOVY))   // 128
#define FARZ 1e10f

#define SH_C0 0.28209479177387814f
#define SH_C1 0.4886025119029199f
#define SH_C2_0 1.0925484305920792f
#define SH_C2_1 (-1.0925484305920792f)
#define SH_C2_2 0.31539156525252005f
#define SH_C2_3 (-1.0925484305920792f)
#define SH_C2_4 0.5462742152960396f
#define SH_C3_0 (-0.5900435899266435f)
#define SH_C3_1 2.890611442640554f
#define SH_C3_2 (-0.4570457994644657f)
#define SH_C3_3 0.3731763325901154f
#define SH_C3_4 (-0.4570457994644657f)
#define SH_C3_5 1.445305721320277f
#define SH_C3_6 (-0.5900435899266435f)

// Unsorted packed records
__device__ float4 g_upack0[NG];  // px, py, na(-0.5ca), nb(-cb)
__device__ float4 g_upack1[NG];  // nc(-0.5cc), op, cr, cg
__device__ float4 g_upack2[NG];  // cb(blue), invd, rad, id
__device__ float  g_depth[NG];
// Depth-sorted packed records
__device__ float4 g_pack0[NG];
__device__ float4 g_pack1[NG];
__device__ float4 g_pack2[NG];

// Monotone ticket grid barrier (replay-safe: target derived from ticket).
__device__ unsigned int g_bar_ctr = 0;

__device__ __forceinline__ void grid_barrier()
{
    __syncthreads();
    if (threadIdx.x == 0) {
        __threadfence();
        unsigned int ticket = atomicAdd(&g_bar_ctr, 1u);
        unsigned int target = (ticket / GRID + 1u) * GRID;
        unsigned int v;
        do {
            asm volatile("ld.acquire.gpu.u32 %0, [%1];" : "=r"(v) : "l"(&g_bar_ctr));
        } while (v < target);
    }
    __syncthreads();
}

#define CHUNK 256
#define NCHUNK (NG / CHUNK)   // 8

struct RasterSmem {
    float4 A[2][CHUNK];
    float4 B[2][CHUNK];
    float4 C[2][CHUNK];
    int    w[2][8];          // per-producer-warp keep counts (lo 4, hi 4)
};

__global__ void __launch_bounds__(NTHREADS) fused_kernel(
    const float* __restrict__ means3D,
    const float* __restrict__ opacities,
    const float* __restrict__ dc,
    const float* __restrict__ shs,
    const float* __restrict__ scales,
    const float* __restrict__ rotations,
    const float* __restrict__ Vm,
    const float* __restrict__ Pm,
    float* __restrict__ out)
{
    __shared__ float sd[NG];          // phase 2 (8KB)
    __shared__ RasterSmem rs;         // phase 3 (~24KB)

    int tid  = threadIdx.x;
    int warp = tid >> 5;
    int lane = tid & 31;

    // ========================================================
    // Phase 1: preprocess. threads 0..15 own one gaussian each
    // ========================================================
    if (tid < 16) {
        int n = blockIdx.x * 16 + tid;

        float m0 = means3D[3*n+0], m1 = means3D[3*n+1], m2 = means3D[3*n+2];

        float pv0 = m0*Vm[0] + m1*Vm[4] + m2*Vm[8]  + Vm[12];
        float pv1 = m0*Vm[1] + m1*Vm[5] + m2*Vm[9]  + Vm[13];
        float pv2 = m0*Vm[2] + m1*Vm[6] + m2*Vm[10] + Vm[14];

        float ph0 = m0*Pm[0] + m1*Pm[4] + m2*Pm[8]  + Pm[12];
        float ph1 = m0*Pm[1] + m1*Pm[5] + m2*Pm[9]  + Pm[13];
        float ph3 = m0*Pm[3] + m1*Pm[7] + m2*Pm[11] + Pm[15];
        float invw = 1.0f / (ph3 + 1e-7f);
        float px = ((ph0*invw + 1.0f) * IMW - 1.0f) * 0.5f;
        float py = ((ph1*invw + 1.0f) * IMH - 1.0f) * 0.5f;

        float tz = pv2;
        float limx = 1.3f * TANFOVX, limy = 1.3f * TANFOVY;
        float tx = fminf(fmaxf(pv0 / tz, -limx), limx) * tz;
        float ty = fminf(fmaxf(pv1 / tz, -limy), limy) * tz;

        float qr = rotations[4*n+0], qx = rotations[4*n+1],
              qy = rotations[4*n+2], qz = rotations[4*n+3];
        float R00 = 1.f - 2.f*(qy*qy + qz*qz);
        float R01 = 2.f*(qx*qy - qr*qz);
        float R02 = 2.f*(qx*qz + qr*qy);
        float R10 = 2.f*(qx*qy + qr*qz);
        float R11 = 1.f - 2.f*(qx*qx + qz*qz);
        float R12 = 2.f*(qy*qz - qr*qx);
        float R20 = 2.f*(qx*qz - qr*qy);
        float R21 = 2.f*(qy*qz + qr*qx);
        float R22 = 1.f - 2.f*(qx*qx + qy*qy);

        float s0 = scales[3*n+0], s1 = scales[3*n+1], s2 = scales[3*n+2];
        float M00=R00*s0, M01=R01*s1, M02=R02*s2;
        float M10=R10*s0, M11=R11*s1, M12=R12*s2;
        float M20=R20*s0, M21=R21*s1, M22=R22*s2;
        float S00 = M00*M00 + M01*M01 + M02*M02;
        float S01 = M00*M10 + M01*M11 + M02*M12;
        float S02 = M00*M20 + M01*M21 + M02*M22;
        float S11 = M10*M10 + M11*M11 + M12*M12;
        float S12 = M10*M20 + M11*M21 + M12*M22;
        float S22 = M20*M20 + M21*M21 + M22*M22;

        float itz = 1.0f / tz;
        float J00 = FOCAL_X * itz;
        float J02 = -FOCAL_X * tx * itz * itz;
        float J11 = FOCAL_Y * itz;
        float J12 = -FOCAL_Y * ty * itz * itz;

        float T00 = J00*Vm[0] + J02*Vm[2];
        float T01 = J00*Vm[4] + J02*Vm[6];
        float T02 = J00*Vm[8] + J02*Vm[10];
        float T10 = J11*Vm[1] + J12*Vm[2];
        float T11 = J11*Vm[5] + J12*Vm[6];
        float T12 = J11*Vm[9] + J12*Vm[10];

        float A00 = T00*S00 + T01*S01 + T02*S02;
        float A01 = T00*S01 + T01*S11 + T02*S12;
        float A02 = T00*S02 + T01*S12 + T02*S22;
        float B00 = T10*S00 + T11*S01 + T12*S02;
        float B01 = T10*S01 + T11*S11 + T12*S12;
        float B02 = T10*S02 + T11*S12 + T12*S22;

        float cov00 = A00*T00 + A01*T01 + A02*T02;
        float cov01 = A00*T10 + A01*T11 + A02*T12;
        float cov11 = B00*T10 + B01*T11 + B02*T12;

        float a = cov00 + 0.3f;
        float b = cov01;
        float c = cov11 + 0.3f;
        float det = a*c - b*b;
        bool valid = (tz > 0.2f) && (det > 0.0f);
        float det_inv = (det > 0.0f) ? (1.0f / det) : 0.0f;

        float mid = 0.5f * (a + c);
        float lam1 = mid + sqrtf(fmaxf(0.1f, mid*mid - det));
        float radius = ceilf(3.0f * sqrtf(lam1));

        float invn = rsqrtf(m0*m0 + m1*m1 + m2*m2);
        float dX = m0*invn, dY = m1*invn, dZ = m2*invn;
        float xx = dX*dX, yy = dY*dY, zz = dZ*dZ;
        float xy = dX*dY, yz = dY*dZ, xz = dX*dZ;

        float col[3];
        #pragma unroll
        for (int ch = 0; ch < 3; ch++) {
            const float* sh = shs + (size_t)n*45 + ch;
            float res = SH_C0 * dc[3*n + ch];
            res += -SH_C1 * dY * sh[0*3] + SH_C1 * dZ * sh[1*3] - SH_C1 * dX * sh[2*3];
            res += SH_C2_0 * xy * sh[3*3] + SH_C2_1 * yz * sh[4*3]
                 + SH_C2_2 * (2.f*zz - xx - yy) * sh[5*3]
                 + SH_C2_3 * xz * sh[6*3] + SH_C2_4 * (xx - yy) * sh[7*3];
            res += SH_C3_0 * dY * (3.f*xx - yy) * sh[8*3]
                 + SH_C3_1 * xy * dZ * sh[9*3]
                 + SH_C3_2 * dY * (4.f*zz - xx - yy) * sh[10*3]
                 + SH_C3_3 * dZ * (2.f*zz - 3.f*xx - 3.f*yy) * sh[11*3]
                 + SH_C3_4 * dX * (4.f*zz - xx - yy) * sh[12*3]
                 + SH_C3_5 * dZ * (xx - yy) * sh[13*3]
                 + SH_C3_6 * dX * (xx - 3.f*yy) * sh[14*3];
            col[ch] = fmaxf(res + 0.5f, 0.0f);
        }

        float depth = valid ? tz : FARZ;
        float rad   = valid ? radius : 0.0f;

        // folded conic: power = na*dx^2 + nc*dy^2 + nb*dx*dy
        float ca = c * det_inv, cbq = -b * det_inv, ccq = a * det_inv;
        g_upack0[n] = make_float4(px, py, -0.5f * ca, -cbq);
        g_upack1[n] = make_float4(-0.5f * ccq, opacities[n], col[0], col[1]);
        g_upack2[n] = make_float4(col[2], 1.0f / depth, rad, (float)n);
        g_depth[n]  = depth;

        out[5*HW + n] = rad;   // radii
    }

    grid_barrier();

    // ========================================================
    // Phase 2: stable rank-count argsort + scatter.
    // 16 gaussians/block over 8 warps -> 2 rounds each.
    // ========================================================
    #pragma unroll
    for (int i = tid; i < NG; i += NTHREADS) sd[i] = g_depth[i];
    __syncthreads();

    #pragma unroll
    for (int r = 0; r < 2; r++) {
        int gi = blockIdx.x * 16 + warp * 2 + r;
        float di = sd[gi];
        int cnt = 0;
        #pragma unroll 8
        for (int j = lane; j < NG; j += 32) {
            float dj = sd[j];
            cnt += (dj < di) || (dj == di && j < gi);
        }
        #pragma unroll
        for (int o = 16; o > 0; o >>= 1) cnt += __shfl_down_sync(0xffffffffu, cnt, o);
        if (lane == 0) {
            g_pack0[cnt] = g_upack0[gi];
            g_pack1[cnt] = g_upack1[gi];
            g_pack2[cnt] = g_upack2[gi];
        }
    }

    grid_barrier();

    // ========================================================
    // Phase 3: warp-specialized raster (R7 structure).
    // Warps 0-3: consumers; warps 4-7: producers.
    // Blend loop software-pipelined: next record prefetched to
    // registers before current is computed.
    // ========================================================
    bool producer = (tid >= 128);
    int bx = blockIdx.x & 7;
    int by = blockIdx.x >> 3;

    float tx0 = (float)(bx * 16);
    float tx1 = tx0 + 15.0f;
    float ty0 = (float)(by * 8);
    float ty1 = ty0 + 7.0f;

    int lx = tid & 15;
    int ly = (tid >> 4) & 7;
    int x = bx * 16 + lx;
    int y = by * 8 + ly;
    float fx = (float)x, fy = (float)y;

    float T = producer ? 0.0f : 1.0f;   // producers always vote "done"
    float cr = 0.f, cg = 0.f, cb = 0.f, invd = 0.f;
    float maxw = 0.f;
    float best = -1.0f;

    int ptid = tid - 128;
    int pw   = warp - 4;

    auto fill = [&](int c, int b) {
        int i0 = c * CHUNK + ptid;
        int i1 = i0 + 128;
        float4 a0 = g_pack0[i0], b0 = g_pack1[i0], c0 = g_pack2[i0];
        float4 a1 = g_pack0[i1], b1 = g_pack1[i1], c1 = g_pack2[i1];

        float r0 = c0.z, r1 = c1.z;
        bool k0 = (r0 > 0.0f) && (a0.x >= tx0 - r0) && (a0.x <= tx1 + r0) &&
                                 (a0.y >= ty0 - r0) && (a0.y <= ty1 + r0);
        bool k1 = (r1 > 0.0f) && (a1.x >= tx0 - r1) && (a1.x <= tx1 + r1) &&
                                 (a1.y >= ty0 - r1) && (a1.y <= ty1 + r1);

        unsigned int m0 = __ballot_sync(0xffffffffu, k0);
        unsigned int m1 = __ballot_sync(0xffffffffu, k1);
        if (lane == 0) { rs.w[b][pw] = __popc(m0); rs.w[b][4 + pw] = __popc(m1); }
        asm volatile("bar.sync 8, 128;" ::: "memory");   // producers only

        int off0 = 0, cnt0 = 0, off1 = 0;
        #pragma unroll
        for (int w = 0; w < 4; w++) {
            int c_lo = rs.w[b][w], c_hi = rs.w[b][4 + w];
            if (w < pw) { off0 += c_lo; off1 += c_hi; }
            cnt0 += c_lo;
        }
        if (k0) {
            int pos = off0 + __popc(m0 & ((1u << lane) - 1u));
            rs.A[b][pos] = a0; rs.B[b][pos] = b0; rs.C[b][pos] = c0;
        }
        if (k1) {
            int pos = cnt0 + off1 + __popc(m1 & ((1u << lane) - 1u));
            rs.A[b][pos] = a1; rs.B[b][pos] = b1; rs.C[b][pos] = c1;
        }
    };

    if (producer) fill(0, 0);
    __syncthreads();

    for (int c = 0; c < NCHUNK; c++) {
        int buf = c & 1;

        if (producer) {
            if (c + 1 < NCHUNK) fill(c + 1, buf ^ 1);
        } else {
            int total = rs.w[buf][0] + rs.w[buf][1] + rs.w[buf][2] + rs.w[buf][3]
                      + rs.w[buf][4] + rs.w[buf][5] + rs.w[buf][6] + rs.w[buf][7];
            if (T >= 1e-4f && total > 0) {
                // software-pipelined blend: prefetch g+1 before computing g
                float4 A = rs.A[buf][0];
                float4 B = rs.B[buf][0];
                float4 C = rs.C[buf][0];
                for (int g = 0; g < total; g++) {
                    int gn = (g + 1 < total) ? (g + 1) : g;
                    float4 A2 = rs.A[buf][gn];
                    float4 B2 = rs.B[buf][gn];
                    float4 C2 = rs.C[buf][gn];

                    float dx = fx - A.x;
                    float dy = fy - A.y;
                    float r  = C.z;
                    float power = fmaf(A.z, dx*dx, fmaf(B.x, dy*dy, A.w*(dx*dy)));
                    float alpha = fminf(0.99f, B.y * __expf(power));
                    bool ok = (fabsf(dx) <= r) & (fabsf(dy) <= r) &
                              (power <= 0.0f) & (alpha >= (1.0f/255.0f));
                    float a = ok ? alpha : 0.0f;
                    float w = a * T;
                    cr   += w * B.z;
                    cg   += w * B.w;
                    cb   += w * C.x;
                    invd += w * C.y;
                    bool better = (w > maxw);
                    maxw = better ? w : maxw;
                    best = better ? C.w : best;
                    T = T * (1.0f - a);

                    A = A2; B = B2; C = C2;
                }
            }
        }
        if (__syncthreads_and(T < 1e-4f)) break;
    }

    if (!producer) {
        int pix = y * IMW + x;
        out[0*HW + pix] = cr;
        out[1*HW + pix] = cg;
        out[2*HW + pix] = cb;
        out[3*HW + pix] = invd;
        out[4*HW + pix] = (maxw > 0.0f) ? best : -1.0f;
    }
}

extern "C" void kernel_launch(void* const* d_in, const int* in_sizes, int n_in,
                              void* d_out, int out_size)
{
    (void)in_sizes; (void)n_in; (void)out_size;
    const float* means3D   = (const float*)d_in[0];
    const float* opacities = (const float*)d_in[2];
    const float* dc        = (const float*)d_in[3];
    const float* shs       = (const float*)d_in[4];
    const float* scales    = (const float*)d_in[5];
    const float* rotations = (const float*)d_in[6];
    const float* viewm     = (const float*)d_in[7];
    const float* projm     = (const float*)d_in[8];
    float* out = (float*)d_out;

    fused_kernel<<<GRID, NTHREADS>>>(means3D, opacities, dc, shs, scales,
                                     rotations, viewm, projm, out);
}